// round 3
// baseline (speedup 1.0000x reference)
#include <cuda_runtime.h>
#include <math.h>

#define SEQ    1024
#define CDIM   768
#define BATCH  8
#define NHEADS 12
#define HD     64
#define BHN    (BATCH*NHEADS)
#define SCALEF 0.125f

// Scratch (allowed: __device__ globals). q/k/v in [B, H, N, hd]; ao in [B, N, C].
__device__ float g_q[(size_t)BHN*SEQ*HD];
__device__ float g_k[(size_t)BHN*SEQ*HD];
__device__ float g_v[(size_t)BHN*SEQ*HD];
__device__ float g_ao[(size_t)BATCH*SEQ*CDIM];

// ---------------------------------------------------------------------------
// GEMM: C[M,N] = A[M,K] @ W[N,K]^T + bias[N]
// BM=BN=128, BK=16, 256 threads, 8x8 micro-tile, spread mapping.
// MODE 0: A = x, scatter output into g_q/g_k/g_v ([B,H,N,hd])
// MODE 1: A = g_ao (device global), write plain row-major to Cout
// ---------------------------------------------------------------------------
template<int MODE>
__global__ __launch_bounds__(256, 2)
void gemm_kernel(const float* __restrict__ A, const float* __restrict__ W,
                 const float* __restrict__ bias, float* __restrict__ Cout,
                 int M, int N, int K)
{
    __shared__ float As[128][20];   // pad 20: row r -> bank base (4r)%32
    __shared__ float Ws[128][20];

    const int tid = threadIdx.x;
    const int ty  = tid >> 4;       // 0..15
    const int tx  = tid & 15;       // 0..15
    const int m0  = blockIdx.y * 128;
    const int n0  = blockIdx.x * 128;
    const int NT  = K >> 4;

    const float* Ap = (MODE == 1) ? (const float*)g_ao : A;
    const float* Ag = Ap + (size_t)m0 * K;
    const float* Wg = W  + (size_t)n0 * K;

    const int lrow = tid >> 2;          // 0..63
    const int lk4  = (tid & 3) << 2;    // 0,4,8,12

    // prefetch tile 0
    float4 pa0 = *(const float4*)(Ag + (size_t)lrow      * K + lk4);
    float4 pa1 = *(const float4*)(Ag + (size_t)(lrow+64) * K + lk4);
    float4 pw0 = *(const float4*)(Wg + (size_t)lrow      * K + lk4);
    float4 pw1 = *(const float4*)(Wg + (size_t)(lrow+64) * K + lk4);
    *(float4*)(&As[lrow     ][lk4]) = pa0;
    *(float4*)(&As[lrow + 64][lk4]) = pa1;
    *(float4*)(&Ws[lrow     ][lk4]) = pw0;
    *(float4*)(&Ws[lrow + 64][lk4]) = pw1;
    __syncthreads();

    float acc[8][8];
    #pragma unroll
    for (int i = 0; i < 8; i++)
        #pragma unroll
        for (int j = 0; j < 8; j++) acc[i][j] = 0.f;

    for (int t = 0; t < NT; t++) {
        if (t + 1 < NT) {
            const int ko = (t + 1) * 16 + lk4;
            pa0 = *(const float4*)(Ag + (size_t)lrow      * K + ko);
            pa1 = *(const float4*)(Ag + (size_t)(lrow+64) * K + ko);
            pw0 = *(const float4*)(Wg + (size_t)lrow      * K + ko);
            pw1 = *(const float4*)(Wg + (size_t)(lrow+64) * K + ko);
        }
        #pragma unroll
        for (int kk = 0; kk < 16; kk++) {
            float a[8], b[8];
            #pragma unroll
            for (int i = 0; i < 8; i++) a[i] = As[ty + 16*i][kk];   // broadcast
            #pragma unroll
            for (int j = 0; j < 8; j++) b[j] = Ws[tx + 16*j][kk];   // 2-way
            #pragma unroll
            for (int i = 0; i < 8; i++)
                #pragma unroll
                for (int j = 0; j < 8; j++)
                    acc[i][j] += a[i] * b[j];
        }
        __syncthreads();
        if (t + 1 < NT) {
            *(float4*)(&As[lrow     ][lk4]) = pa0;
            *(float4*)(&As[lrow + 64][lk4]) = pa1;
            *(float4*)(&Ws[lrow     ][lk4]) = pw0;
            *(float4*)(&Ws[lrow + 64][lk4]) = pw1;
            __syncthreads();
        }
    }

    if (MODE == 0) {
        // column j of QKV output decomposes as (t, head, d): j = t*768 + h*64 + d
        const int tsel = n0 / CDIM;   // constant per block (768 = 6*128)
        float* dst = (tsel == 0) ? g_q : (tsel == 1) ? g_k : g_v;
        const int b = m0 >> 10;       // constant per block (1024 = 8*128)
        #pragma unroll
        for (int i = 0; i < 8; i++) {
            const int m = m0 + ty + 16*i;
            const int n = m & (SEQ - 1);
            #pragma unroll
            for (int j = 0; j < 8; j++) {
                const int col = n0 + tx + 16*j;
                const int rem = col - tsel * CDIM;
                const int h = rem >> 6;
                const int d = rem & 63;
                dst[(((size_t)b * NHEADS + h) * SEQ + n) * HD + d] = acc[i][j] + bias[col];
            }
        }
    } else {
        #pragma unroll
        for (int i = 0; i < 8; i++) {
            const int r = m0 + ty + 16*i;
            #pragma unroll
            for (int j = 0; j < 8; j++) {
                const int c = n0 + tx + 16*j;
                Cout[(size_t)r * N + c] = acc[i][j] + bias[c];
            }
        }
    }
}

// ---------------------------------------------------------------------------
// Fused flash-style attention. Grid (SEQ/64, B*H), 256 threads.
// Per block: 64 Q rows x hd=64; loop over 16 key tiles of 64.
// SMEM pad 68 makes all inner LDS.128 conflict-free or 2-way.
// Writes output directly in [B, N, C] layout (proj GEMM reads it plain).
// ---------------------------------------------------------------------------
__global__ __launch_bounds__(256, 2)
void attn_kernel()
{
    extern __shared__ float sm[];
    float* Qs = sm;                 // [64][68]
    float* Ks = sm + 64 * 68;       // [64][68]
    float* Vs = sm + 2 * 64 * 68;   // [64][68]
    float* Ps = sm + 3 * 64 * 68;   // [64][68]

    const int tid = threadIdx.x;
    const int ty  = tid >> 4;       // 0..15 -> rows 4*ty..4*ty+3
    const int tx  = tid & 15;       // 0..15
    const int bh  = blockIdx.y;
    const int qt  = blockIdx.x;

    const float* qg = g_q + (size_t)bh * SEQ * HD + (size_t)qt * 64 * HD;
    const float* kg = g_k + (size_t)bh * SEQ * HD;
    const float* vg = g_v + (size_t)bh * SEQ * HD;

    // load Q tile once (16 floats / thread)
    #pragma unroll
    for (int rep = 0; rep < 4; rep++) {
        int lin = tid + rep * 256;
        int row = lin >> 4;
        int d4  = (lin & 15) << 2;
        *(float4*)(Qs + row * 68 + d4) = *(const float4*)(qg + row * HD + d4);
    }

    float m_i[4], l_i[4], o[4][4];
    #pragma unroll
    for (int i = 0; i < 4; i++) {
        m_i[i] = -1e30f; l_i[i] = 0.f;
        #pragma unroll
        for (int j = 0; j < 4; j++) o[i][j] = 0.f;
    }

    for (int kt = 0; kt < SEQ / 64; kt++) {
        const float* kgt = kg + (size_t)kt * 64 * HD;
        const float* vgt = vg + (size_t)kt * 64 * HD;
        #pragma unroll
        for (int rep = 0; rep < 4; rep++) {
            int lin = tid + rep * 256;
            int row = lin >> 4;
            int d4  = (lin & 15) << 2;
            *(float4*)(Ks + row * 68 + d4) = *(const float4*)(kgt + row * HD + d4);
            *(float4*)(Vs + row * 68 + d4) = *(const float4*)(vgt + row * HD + d4);
        }
        __syncthreads();

        // S = Q @ K^T for rows 4ty..4ty+3, cols tx+16j
        float s[4][4];
        #pragma unroll
        for (int i = 0; i < 4; i++)
            #pragma unroll
            for (int j = 0; j < 4; j++) s[i][j] = 0.f;

        #pragma unroll
        for (int d4 = 0; d4 < 16; d4++) {
            float4 q4[4], k4[4];
            #pragma unroll
            for (int i = 0; i < 4; i++)
                q4[i] = *(float4*)(Qs + (4*ty + i) * 68 + d4 * 4);   // broadcast
            #pragma unroll
            for (int j = 0; j < 4; j++)
                k4[j] = *(float4*)(Ks + (tx + 16*j) * 68 + d4 * 4);  // 2-way
            #pragma unroll
            for (int i = 0; i < 4; i++)
                #pragma unroll
                for (int j = 0; j < 4; j++) {
                    s[i][j] += q4[i].x * k4[j].x;
                    s[i][j] += q4[i].y * k4[j].y;
                    s[i][j] += q4[i].z * k4[j].z;
                    s[i][j] += q4[i].w * k4[j].w;
                }
        }

        // online softmax (row state replicated across the 16 tx lanes)
        #pragma unroll
        for (int i = 0; i < 4; i++) {
            #pragma unroll
            for (int j = 0; j < 4; j++) s[i][j] *= SCALEF;
            float rm = fmaxf(fmaxf(s[i][0], s[i][1]), fmaxf(s[i][2], s[i][3]));
            #pragma unroll
            for (int off = 1; off < 16; off <<= 1)
                rm = fmaxf(rm, __shfl_xor_sync(0xffffffffu, rm, off));
            const float mnew = fmaxf(m_i[i], rm);
            const float corr = __expf(m_i[i] - mnew);
            float rs = 0.f;
            #pragma unroll
            for (int j = 0; j < 4; j++) {
                float p = __expf(s[i][j] - mnew);
                s[i][j] = p;
                rs += p;
            }
            #pragma unroll
            for (int off = 1; off < 16; off <<= 1)
                rs += __shfl_xor_sync(0xffffffffu, rs, off);
            l_i[i] = l_i[i] * corr + rs;
            m_i[i] = mnew;
            #pragma unroll
            for (int j = 0; j < 4; j++) o[i][j] *= corr;
        }

        // stage P (conflict-free scalar stores)
        #pragma unroll
        for (int i = 0; i < 4; i++)
            #pragma unroll
            for (int j = 0; j < 4; j++)
                Ps[(4*ty + i) * 68 + tx + 16*j] = s[i][j];
        __syncthreads();

        // O += P @ V   (rows 4ty..4ty+3, dims 4tx..4tx+3)
        #pragma unroll
        for (int c4 = 0; c4 < 16; c4++) {
            float p[4][4];
            #pragma unroll
            for (int i = 0; i < 4; i++) {
                float4 t4 = *(float4*)(Ps + (4*ty + i) * 68 + c4 * 4);  // broadcast
                p[i][0] = t4.x; p[i][1] = t4.y; p[i][2] = t4.z; p[i][3] = t4.w;
            }
            #pragma unroll
            for (int cc = 0; cc < 4; cc++) {
                float4 v4 = *(float4*)(Vs + (c4 * 4 + cc) * 68 + tx * 4);  // 2-way
                #pragma unroll
                for (int i = 0; i < 4; i++) {
                    o[i][0] += p[i][cc] * v4.x;
                    o[i][1] += p[i][cc] * v4.y;
                    o[i][2] += p[i][cc] * v4.z;
                    o[i][3] += p[i][cc] * v4.w;
                }
            }
        }
        __syncthreads();
    }

    // normalize + write in [B, N, C] layout
    const int b = bh / NHEADS;
    const int h = bh % NHEADS;
    #pragma unroll
    for (int i = 0; i < 4; i++) {
        const float inv = 1.0f / l_i[i];
        const int row = qt * 64 + 4*ty + i;
        float4 r4;
        r4.x = o[i][0] * inv;
        r4.y = o[i][1] * inv;
        r4.z = o[i][2] * inv;
        r4.w = o[i][3] * inv;
        *(float4*)(g_ao + ((size_t)b * SEQ + row) * CDIM + h * HD + tx * 4) = r4;
    }
}

// ---------------------------------------------------------------------------
// Inputs (metadata order): x, qkv_w, qkv_b, proj_w, proj_b, H, W
// ---------------------------------------------------------------------------
extern "C" void kernel_launch(void* const* d_in, const int* in_sizes, int n_in,
                              void* d_out, int out_size)
{
    (void)in_sizes; (void)n_in; (void)out_size;
    const float* x      = (const float*)d_in[0];
    const float* qkv_w  = (const float*)d_in[1];
    const float* qkv_b  = (const float*)d_in[2];
    const float* proj_w = (const float*)d_in[3];
    const float* proj_b = (const float*)d_in[4];
    float* out = (float*)d_out;

    const int smem_attn = 4 * 64 * 68 * (int)sizeof(float);  // 69632 B
    cudaFuncSetAttribute(attn_kernel, cudaFuncAttributeMaxDynamicSharedMemorySize, smem_attn);

    // 1) QKV GEMM + bias, scatter into per-head q/k/v
    gemm_kernel<0><<<dim3(3 * CDIM / 128, (BATCH * SEQ) / 128), 256>>>(
        x, qkv_w, qkv_b, nullptr, BATCH * SEQ, 3 * CDIM, CDIM);

    // 2) fused attention -> g_ao in [B, N, C]
    attn_kernel<<<dim3(SEQ / 64, BHN), 256, smem_attn>>>();

    // 3) proj GEMM + bias -> d_out
    gemm_kernel<1><<<dim3(CDIM / 128, (BATCH * SEQ) / 128), 256>>>(
        nullptr, proj_w, proj_b, out, BATCH * SEQ, CDIM, CDIM);
}

// round 6
// speedup vs baseline: 2.9889x; 2.9889x over previous
#include <cuda_runtime.h>
#include <math.h>

#define SEQ    1024
#define CDIM   768
#define BATCH  8
#define NHEADS 12
#define HD     64
#define BHN    (BATCH*NHEADS)
#define SCALEF 0.125f

// Scratch: q/k/v in [B, H, N, hd]; ao in [B, N, C].
__device__ float g_q[(size_t)BHN*SEQ*HD];
__device__ float g_k[(size_t)BHN*SEQ*HD];
__device__ float g_v[(size_t)BHN*SEQ*HD];
__device__ float g_ao[(size_t)BATCH*SEQ*CDIM];

__device__ __forceinline__ unsigned f2tf32(float f) {
    unsigned u;
    asm("cvt.rna.tf32.f32 %0, %1;" : "=r"(u) : "f"(f));
    return u;
}

__device__ __forceinline__ void mma_tf32(float c[4], const unsigned a[4],
                                         unsigned b0, unsigned b1) {
    asm volatile(
        "mma.sync.aligned.m16n8k8.row.col.f32.tf32.tf32.f32 "
        "{%0,%1,%2,%3}, {%4,%5,%6,%7}, {%8,%9}, {%0,%1,%2,%3};\n"
        : "+f"(c[0]), "+f"(c[1]), "+f"(c[2]), "+f"(c[3])
        : "r"(a[0]), "r"(a[1]), "r"(a[2]), "r"(a[3]), "r"(b0), "r"(b1));
}

// ---------------------------------------------------------------------------
// Tensor-core GEMM: C[M,N] = A[M,K] @ W[N,K]^T + bias[N]
// BM=BN=128, BK=32, 256 threads = 8 warps (2x4), warp tile 64x32.
// MODE 0: A = x, scatter into g_q/g_k/g_v.  MODE 1: A = g_ao, plain output.
// ---------------------------------------------------------------------------
template<int MODE>
__global__ __launch_bounds__(256)
void gemm_tc(const float* __restrict__ A, const float* __restrict__ W,
             const float* __restrict__ bias, float* __restrict__ Cout,
             int M, int N, int K)
{
    __shared__ unsigned As[128][36];   // stride 36: frag LDS conflict-free
    __shared__ unsigned Ws[128][36];

    const int tid  = threadIdx.x;
    const int lane = tid & 31, warp = tid >> 5;
    const int g    = lane >> 2, tig = lane & 3;
    const int wm   = (warp >> 2) * 64;
    const int wn   = (warp & 3) * 32;
    const int m0   = blockIdx.y * 128;
    const int n0   = blockIdx.x * 128;

    const float* Ap = (MODE == 1) ? (const float*)g_ao : A;
    const float* Ag = Ap + (size_t)m0 * K;
    const float* Wg = W  + (size_t)n0 * K;

    const int lrow = tid >> 1;        // 0..127
    const int lcb  = (tid & 1) * 16;  // 0 / 16

    float4 pa[4], pw[4];
    #pragma unroll
    for (int u = 0; u < 4; u++) {
        pa[u] = *(const float4*)(Ag + (size_t)lrow * K + lcb + 4*u);
        pw[u] = *(const float4*)(Wg + (size_t)lrow * K + lcb + 4*u);
    }
    #pragma unroll
    for (int u = 0; u < 4; u++) {
        As[lrow][lcb+4*u+0] = f2tf32(pa[u].x); As[lrow][lcb+4*u+1] = f2tf32(pa[u].y);
        As[lrow][lcb+4*u+2] = f2tf32(pa[u].z); As[lrow][lcb+4*u+3] = f2tf32(pa[u].w);
        Ws[lrow][lcb+4*u+0] = f2tf32(pw[u].x); Ws[lrow][lcb+4*u+1] = f2tf32(pw[u].y);
        Ws[lrow][lcb+4*u+2] = f2tf32(pw[u].z); Ws[lrow][lcb+4*u+3] = f2tf32(pw[u].w);
    }
    __syncthreads();

    float acc[4][4][4];
    #pragma unroll
    for (int mi = 0; mi < 4; mi++)
        #pragma unroll
        for (int nj = 0; nj < 4; nj++)
            #pragma unroll
            for (int c = 0; c < 4; c++) acc[mi][nj][c] = 0.f;

    const int NT = K / 32;
    for (int t = 0; t < NT; t++) {
        if (t + 1 < NT) {
            const int ko = (t + 1) * 32 + lcb;
            #pragma unroll
            for (int u = 0; u < 4; u++) {
                pa[u] = *(const float4*)(Ag + (size_t)lrow * K + ko + 4*u);
                pw[u] = *(const float4*)(Wg + (size_t)lrow * K + ko + 4*u);
            }
        }
        #pragma unroll
        for (int ks = 0; ks < 4; ks++) {
            unsigned afr[4][4];
            #pragma unroll
            for (int mi = 0; mi < 4; mi++) {
                const int r = wm + 16*mi;
                afr[mi][0] = As[r + g    ][8*ks + tig];
                afr[mi][1] = As[r + 8 + g][8*ks + tig];
                afr[mi][2] = As[r + g    ][8*ks + tig + 4];
                afr[mi][3] = As[r + 8 + g][8*ks + tig + 4];
            }
            #pragma unroll
            for (int nj = 0; nj < 4; nj++) {
                const unsigned b0 = Ws[wn + 8*nj + g][8*ks + tig];
                const unsigned b1 = Ws[wn + 8*nj + g][8*ks + tig + 4];
                #pragma unroll
                for (int mi = 0; mi < 4; mi++)
                    mma_tf32(acc[mi][nj], afr[mi], b0, b1);
            }
        }
        __syncthreads();
        if (t + 1 < NT) {
            #pragma unroll
            for (int u = 0; u < 4; u++) {
                As[lrow][lcb+4*u+0] = f2tf32(pa[u].x); As[lrow][lcb+4*u+1] = f2tf32(pa[u].y);
                As[lrow][lcb+4*u+2] = f2tf32(pa[u].z); As[lrow][lcb+4*u+3] = f2tf32(pa[u].w);
                Ws[lrow][lcb+4*u+0] = f2tf32(pw[u].x); Ws[lrow][lcb+4*u+1] = f2tf32(pw[u].y);
                Ws[lrow][lcb+4*u+2] = f2tf32(pw[u].z); Ws[lrow][lcb+4*u+3] = f2tf32(pw[u].w);
            }
            __syncthreads();
        }
    }

    // bias per nj (col depends only on nj within the warp tile)
    float2 bv[4];
    int colv[4];
    #pragma unroll
    for (int nj = 0; nj < 4; nj++) {
        const int col = n0 + wn + 8*nj + 2*tig;
        colv[nj] = col;
        bv[nj].x = bias[col];
        bv[nj].y = bias[col + 1];
    }

    if (MODE == 0) {
        const int tsel = n0 / CDIM;   // constant per block (768 % 128 == 0)
        float* dst = (tsel == 0) ? g_q : (tsel == 1) ? g_k : g_v;
        const int b = m0 >> 10;       // constant per block
        #pragma unroll
        for (int mi = 0; mi < 4; mi++) {
            #pragma unroll
            for (int rr = 0; rr < 2; rr++) {
                const int row = m0 + wm + 16*mi + g + 8*rr;
                const int n   = row & (SEQ - 1);
                #pragma unroll
                for (int nj = 0; nj < 4; nj++) {
                    const int rem = colv[nj] - tsel * CDIM;
                    const int h = rem >> 6;
                    const int d = rem & 63;
                    float2 v;
                    v.x = acc[mi][nj][2*rr + 0] + bv[nj].x;
                    v.y = acc[mi][nj][2*rr + 1] + bv[nj].y;
                    *(float2*)&dst[(((size_t)b * NHEADS + h) * SEQ + n) * HD + d] = v;
                }
            }
        }
    } else {
        #pragma unroll
        for (int mi = 0; mi < 4; mi++) {
            #pragma unroll
            for (int rr = 0; rr < 2; rr++) {
                const int row = m0 + wm + 16*mi + g + 8*rr;
                #pragma unroll
                for (int nj = 0; nj < 4; nj++) {
                    float2 v;
                    v.x = acc[mi][nj][2*rr + 0] + bv[nj].x;
                    v.y = acc[mi][nj][2*rr + 1] + bv[nj].y;
                    *(float2*)&Cout[(size_t)row * N + colv[nj]] = v;
                }
            }
        }
    }
}

// ---------------------------------------------------------------------------
// Fused flash attention on tensor cores.
// Grid (SEQ/128, B*H), 256 threads = 8 warps; warp w owns rows 16w..16w+15.
// Q fragments register-resident across all 16 K-tiles. Q SMEM reused for P.
// ---------------------------------------------------------------------------
__global__ __launch_bounds__(256)
void attn_tc()
{
    extern __shared__ unsigned sm[];
    unsigned* QPs = sm;                        // [128][68]  Q, then P
    unsigned* Ks  = sm + 128 * 68;             // [64][68]
    unsigned* Vs  = sm + 128 * 68 + 64 * 68;   // [64][72]

    const int tid  = threadIdx.x;
    const int lane = tid & 31, warp = tid >> 5;
    const int g    = lane >> 2, tig = lane & 3;
    const int bh   = blockIdx.y;
    const int qt   = blockIdx.x;

    const float* qg = g_q + (size_t)bh * SEQ * HD + (size_t)qt * 128 * HD;
    const float* kg = g_k + (size_t)bh * SEQ * HD;
    const float* vg = g_v + (size_t)bh * SEQ * HD;

    // load Q 128x64 (tf32-converted)
    {
        const int row = tid >> 1;
        const int cb  = (tid & 1) * 32;
        #pragma unroll
        for (int u = 0; u < 8; u++) {
            float4 f = *(const float4*)(qg + (size_t)row * HD + cb + 4*u);
            QPs[row*68 + cb + 4*u + 0] = f2tf32(f.x);
            QPs[row*68 + cb + 4*u + 1] = f2tf32(f.y);
            QPs[row*68 + cb + 4*u + 2] = f2tf32(f.z);
            QPs[row*68 + cb + 4*u + 3] = f2tf32(f.w);
        }
    }
    __syncthreads();

    // Q fragments: register-resident for the whole kernel
    unsigned aq[8][4];
    {
        const int r = 16 * warp;
        #pragma unroll
        for (int ks = 0; ks < 8; ks++) {
            aq[ks][0] = QPs[(r + g    ) * 68 + 8*ks + tig];
            aq[ks][1] = QPs[(r + 8 + g) * 68 + 8*ks + tig];
            aq[ks][2] = QPs[(r + g    ) * 68 + 8*ks + tig + 4];
            aq[ks][3] = QPs[(r + 8 + g) * 68 + 8*ks + tig + 4];
        }
    }
    __syncthreads();

    float o[8][4];
    #pragma unroll
    for (int nj = 0; nj < 8; nj++)
        #pragma unroll
        for (int c = 0; c < 4; c++) o[nj][c] = 0.f;
    float m0r = -1e30f, m1r = -1e30f, l0 = 0.f, l1 = 0.f;

    for (int kt = 0; kt < SEQ / 64; kt++) {
        // load K,V 64x64 each (tf32-converted)
        {
            const int row = tid >> 2;
            const int cb  = (tid & 3) * 16;
            const float* kp = kg + (size_t)(kt*64 + row) * HD + cb;
            const float* vp = vg + (size_t)(kt*64 + row) * HD + cb;
            #pragma unroll
            for (int u = 0; u < 4; u++) {
                float4 fk = *(const float4*)(kp + 4*u);
                float4 fv = *(const float4*)(vp + 4*u);
                Ks[row*68 + cb + 4*u + 0] = f2tf32(fk.x);
                Ks[row*68 + cb + 4*u + 1] = f2tf32(fk.y);
                Ks[row*68 + cb + 4*u + 2] = f2tf32(fk.z);
                Ks[row*68 + cb + 4*u + 3] = f2tf32(fk.w);
                Vs[row*72 + cb + 4*u + 0] = f2tf32(fv.x);
                Vs[row*72 + cb + 4*u + 1] = f2tf32(fv.y);
                Vs[row*72 + cb + 4*u + 2] = f2tf32(fv.z);
                Vs[row*72 + cb + 4*u + 3] = f2tf32(fv.w);
            }
        }
        __syncthreads();

        // S = Q @ K^T  (m16 x n64)
        float s[8][4];
        #pragma unroll
        for (int nj = 0; nj < 8; nj++)
            #pragma unroll
            for (int c = 0; c < 4; c++) s[nj][c] = 0.f;

        #pragma unroll
        for (int ks = 0; ks < 8; ks++) {
            #pragma unroll
            for (int nj = 0; nj < 8; nj++) {
                const unsigned b0 = Ks[(8*nj + g) * 68 + 8*ks + tig];
                const unsigned b1 = Ks[(8*nj + g) * 68 + 8*ks + tig + 4];
                mma_tf32(s[nj], aq[ks], b0, b1);
            }
        }

        // online softmax: thread owns rows r0=16w+g (c0,c1), r1=r0+8 (c2,c3)
        float rm0 = -1e30f, rm1 = -1e30f;
        #pragma unroll
        for (int nj = 0; nj < 8; nj++) {
            s[nj][0] *= SCALEF; s[nj][1] *= SCALEF;
            s[nj][2] *= SCALEF; s[nj][3] *= SCALEF;
            rm0 = fmaxf(rm0, fmaxf(s[nj][0], s[nj][1]));
            rm1 = fmaxf(rm1, fmaxf(s[nj][2], s[nj][3]));
        }
        rm0 = fmaxf(rm0, __shfl_xor_sync(0xffffffffu, rm0, 1));
        rm0 = fmaxf(rm0, __shfl_xor_sync(0xffffffffu, rm0, 2));
        rm1 = fmaxf(rm1, __shfl_xor_sync(0xffffffffu, rm1, 1));
        rm1 = fmaxf(rm1, __shfl_xor_sync(0xffffffffu, rm1, 2));

        const float mn0 = fmaxf(m0r, rm0);
        const float mn1 = fmaxf(m1r, rm1);
        const float cr0 = __expf(m0r - mn0);
        const float cr1 = __expf(m1r - mn1);
        float rs0 = 0.f, rs1 = 0.f;
        #pragma unroll
        for (int nj = 0; nj < 8; nj++) {
            s[nj][0] = __expf(s[nj][0] - mn0);
            s[nj][1] = __expf(s[nj][1] - mn0);
            s[nj][2] = __expf(s[nj][2] - mn1);
            s[nj][3] = __expf(s[nj][3] - mn1);
            rs0 += s[nj][0] + s[nj][1];
            rs1 += s[nj][2] + s[nj][3];
        }
        rs0 += __shfl_xor_sync(0xffffffffu, rs0, 1);
        rs0 += __shfl_xor_sync(0xffffffffu, rs0, 2);
        rs1 += __shfl_xor_sync(0xffffffffu, rs1, 1);
        rs1 += __shfl_xor_sync(0xffffffffu, rs1, 2);
        l0 = l0 * cr0 + rs0;  m0r = mn0;
        l1 = l1 * cr1 + rs1;  m1r = mn1;
        #pragma unroll
        for (int nj = 0; nj < 8; nj++) {
            o[nj][0] *= cr0; o[nj][1] *= cr0;
            o[nj][2] *= cr1; o[nj][3] *= cr1;
        }

        // stage P (tf32) into QPs
        {
            const int r0 = 16*warp + g;
            #pragma unroll
            for (int nj = 0; nj < 8; nj++) {
                QPs[ r0      * 68 + 8*nj + 2*tig    ] = f2tf32(s[nj][0]);
                QPs[ r0      * 68 + 8*nj + 2*tig + 1] = f2tf32(s[nj][1]);
                QPs[(r0 + 8) * 68 + 8*nj + 2*tig    ] = f2tf32(s[nj][2]);
                QPs[(r0 + 8) * 68 + 8*nj + 2*tig + 1] = f2tf32(s[nj][3]);
            }
        }
        __syncthreads();

        // O += P @ V
        #pragma unroll
        for (int ks = 0; ks < 8; ks++) {
            unsigned pa[4];
            pa[0] = QPs[(16*warp + g    ) * 68 + 8*ks + tig];
            pa[1] = QPs[(16*warp + 8 + g) * 68 + 8*ks + tig];
            pa[2] = QPs[(16*warp + g    ) * 68 + 8*ks + tig + 4];
            pa[3] = QPs[(16*warp + 8 + g) * 68 + 8*ks + tig + 4];
            #pragma unroll
            for (int nj = 0; nj < 8; nj++) {
                const unsigned b0 = Vs[(8*ks + tig    ) * 72 + 8*nj + g];
                const unsigned b1 = Vs[(8*ks + tig + 4) * 72 + 8*nj + g];
                mma_tf32(o[nj], pa, b0, b1);
            }
        }
        __syncthreads();
    }

    // normalize + write [B, N, C]
    const int b = bh / NHEADS, h = bh % NHEADS;
    const float inv0 = 1.f / l0, inv1 = 1.f / l1;
    const int r0 = qt * 128 + 16*warp + g;
    #pragma unroll
    for (int nj = 0; nj < 8; nj++) {
        const int col = 8*nj + 2*tig;
        float2 v0, v1;
        v0.x = o[nj][0] * inv0; v0.y = o[nj][1] * inv0;
        v1.x = o[nj][2] * inv1; v1.y = o[nj][3] * inv1;
        *(float2*)&g_ao[((size_t)b * SEQ + r0    ) * CDIM + h*HD + col] = v0;
        *(float2*)&g_ao[((size_t)b * SEQ + r0 + 8) * CDIM + h*HD + col] = v1;
    }
}

// ---------------------------------------------------------------------------
// Inputs (metadata order): x, qkv_w, qkv_b, proj_w, proj_b, H, W
// ---------------------------------------------------------------------------
extern "C" void kernel_launch(void* const* d_in, const int* in_sizes, int n_in,
                              void* d_out, int out_size)
{
    (void)in_sizes; (void)n_in; (void)out_size;
    const float* x      = (const float*)d_in[0];
    const float* qkv_w  = (const float*)d_in[1];
    const float* qkv_b  = (const float*)d_in[2];
    const float* proj_w = (const float*)d_in[3];
    const float* proj_b = (const float*)d_in[4];
    float* out = (float*)d_out;

    const int smem_attn = (128*68 + 64*68 + 64*72) * (int)sizeof(unsigned); // 70656
    cudaFuncSetAttribute(attn_tc, cudaFuncAttributeMaxDynamicSharedMemorySize, smem_attn);

    // 1) QKV GEMM + bias -> per-head q/k/v
    gemm_tc<0><<<dim3(3 * CDIM / 128, (BATCH * SEQ) / 128), 256>>>(
        x, qkv_w, qkv_b, nullptr, BATCH * SEQ, 3 * CDIM, CDIM);

    // 2) fused flash attention -> g_ao in [B, N, C]
    attn_tc<<<dim3(SEQ / 128, BHN), 256, smem_attn>>>();

    // 3) proj GEMM + bias -> d_out
    gemm_tc<1><<<dim3(CDIM / 128, (BATCH * SEQ) / 128), 256>>>(
        nullptr, proj_w, proj_b, out, BATCH * SEQ, CDIM, CDIM);
}